// round 12
// baseline (speedup 1.0000x reference)
#include <cuda_runtime.h>
#include <cuda_fp16.h>
#include <cuda_bf16.h>
#include <math_constants.h>
#include <cstdint>

// Problem constants (z: 32*2048*64 fp32, codebook: 1024*64 fp32)
#define N_VEC   65536
#define E_DIM   64
#define N_CODE  1024
#define ELEMS   (N_VEC * E_DIM)
#define CAP     64

// ---------------------------------------------------------------------------
// Global scratch (module globals; no runtime allocation)
// ---------------------------------------------------------------------------
__device__ float    g_cc[N_CODE];
__device__ uint16_t g_cch[N_CODE];            // fp16 bits of cc/2
__device__ __half2  g_cb_h[N_CODE * 32];      // fp16 codebook, [code][32 half2]
__device__ int      g_idx[N_VEC];
__device__ int      g_counts[N_CODE];
__device__ float    g_sse_part[8192];
__device__ int      g_ccount[N_VEC];
__device__ int      g_cand[N_VEC * CAP];

// ---------------------------------------------------------------------------
// helpers — ALL packed fp16 math on plain uint32 registers (no half2 locals)
// ---------------------------------------------------------------------------
__device__ __forceinline__ uint32_t hfma2u(uint32_t a, uint32_t b, uint32_t c) {
    uint32_t d;
    asm("fma.rn.f16x2 %0, %1, %2, %3;" : "=r"(d) : "r"(a), "r"(b), "r"(c));
    return d;
}
__device__ __forceinline__ uint32_t hadd2u(uint32_t a, uint32_t b) {
    uint32_t d;
    asm("add.rn.f16x2 %0, %1, %2;" : "=r"(d) : "r"(a), "r"(b));
    return d;
}
__device__ __forceinline__ uint32_t packn_h2(float x, float y) {   // fp16(-x),fp16(-y)
    __half2_raw r = __floats2half2_rn(-x, -y);
    return (uint32_t)r.x | ((uint32_t)r.y << 16);
}

// exact fp32 dot — identical chain to the rel_err-0.0 passing rounds
__device__ __forceinline__ float dot64(const float4* __restrict__ a,
                                       const float4* __restrict__ b) {
    float s = 0.0f;
#pragma unroll
    for (int i = 0; i < 16; i++) {
        float4 x = a[i], y = b[i];
        s = fmaf(x.x, y.x, s);
        s = fmaf(x.y, y.y, s);
        s = fmaf(x.z, y.z, s);
        s = fmaf(x.w, y.w, s);
    }
    return s;
}

// ---------------------------------------------------------------------------
// Kernel 1: cc norms, fp16 codebook + cc/2, zero histogram. 4 blocks x 256.
// ---------------------------------------------------------------------------
__global__ void vq_prep(const float* __restrict__ cb) {
    const int j = blockIdx.x * 256 + threadIdx.x;     // 0..1023
    const float4* p = reinterpret_cast<const float4*>(cb + (size_t)j * E_DIM);
    float s = 0.0f;
#pragma unroll
    for (int i = 0; i < 16; i++) {
        float4 v = p[i];
        s = fmaf(v.x, v.x, s);
        s = fmaf(v.y, v.y, s);
        s = fmaf(v.z, v.z, s);
        s = fmaf(v.w, v.w, s);
        g_cb_h[j * 32 + 2 * i]     = __floats2half2_rn(v.x, v.y);
        g_cb_h[j * 32 + 2 * i + 1] = __floats2half2_rn(v.z, v.w);
    }
    g_cc[j] = s;
    g_cch[j] = __half_as_ushort(__float2half(0.5f * s));
    g_counts[j] = 0;
}

// ---------------------------------------------------------------------------
// Kernel 2: clean HFMA2 screening. 128 CTAs x 256 threads, 2 rows/thread.
//   Whole fp16 codebook (128 KB) + cc/2 (2 KB) staged in smem once.
//   Score s_j = cc_j/2 + sum((-z)*e)  (== (d_j - zz)/2, same ordering).
//   Track thr = rmin + marg in fp16; emit while s <= thr; exact recheck later.
// ---------------------------------------------------------------------------
#define SMEM_SCREEN (N_CODE * 64 * 2 + N_CODE * 2)    // 133120 B

__global__ void __launch_bounds__(256, 1)
vq_screen(const float* __restrict__ z) {
    extern __shared__ uint4 sE[];                      // 8 uint4 per code
    uint16_t* scch = reinterpret_cast<uint16_t*>(sE + N_CODE * 8);

    const int tid = threadIdx.x;
    const int row0 = blockIdx.x * 512 + tid;
    const int row1 = row0 + 256;

    // stage codebook (8192 uint4, 32 per thread) + cc/2 (as u32 pairs)
    {
        const uint4* src = reinterpret_cast<const uint4*>(g_cb_h);
#pragma unroll
        for (int k = 0; k < 32; k++)
            sE[k * 256 + tid] = src[k * 256 + tid];
        const uint32_t* cs = reinterpret_cast<const uint32_t*>(g_cch);
        uint32_t* cd = reinterpret_cast<uint32_t*>(scch);
#pragma unroll
        for (int k = 0; k < 2; k++)
            cd[k * 256 + tid] = cs[k * 256 + tid];
    }

    // load both z rows -> negated fp16 pair regs (const-indexed, fully unrolled)
    uint32_t uq0[32], uq1[32];
    float sz0 = 0.0f, sz1 = 0.0f;
    {
        const float4* zp0 = reinterpret_cast<const float4*>(z + (size_t)row0 * E_DIM);
        const float4* zp1 = reinterpret_cast<const float4*>(z + (size_t)row1 * E_DIM);
#pragma unroll
        for (int i = 0; i < 16; i++) {
            float4 v = zp0[i];
            sz0 += fabsf(v.x) + fabsf(v.y) + fabsf(v.z) + fabsf(v.w);
            uq0[2 * i]     = packn_h2(v.x, v.y);
            uq0[2 * i + 1] = packn_h2(v.z, v.w);
            float4 w = zp1[i];
            sz1 += fabsf(w.x) + fabsf(w.y) + fabsf(w.z) + fabsf(w.w);
            uq1[2 * i]     = packn_h2(w.x, w.y);
            uq1[2 * i + 1] = packn_h2(w.z, w.w);
        }
    }
    const __half hm0 = __float2half(sz0 * 2e-5f + 2e-4f);   // validated margin form
    const __half hm1 = __float2half(sz1 * 2e-5f + 2e-4f);

    __syncthreads();

    __half thr0 = __ushort_as_half((unsigned short)0x7C00);  // +inf
    __half thr1 = thr0;
    int cnt0 = 0, cnt1 = 0;
    int* cand0 = g_cand + (size_t)row0 * CAP;
    int* cand1 = g_cand + (size_t)row1 * CAP;

#pragma unroll 2
    for (int j = 0; j < N_CODE; j++) {
        const uint4* ep = sE + j * 8;
        const uint32_t seed = (uint32_t)scch[j];      // cc/2 in LOW half
        // 8 named uint4 loads — members used directly, stays in registers
        const uint4 w0 = ep[0], w1 = ep[1], w2 = ep[2], w3 = ep[3];
        const uint4 w4 = ep[4], w5 = ep[5], w6 = ep[6], w7 = ep[7];

        uint32_t a0 = hfma2u(uq0[0], w0.x, seed);
        uint32_t a1 = hfma2u(uq0[1], w0.y, 0u);
        uint32_t b0 = hfma2u(uq1[0], w0.x, seed);
        uint32_t b1 = hfma2u(uq1[1], w0.y, 0u);
        a0 = hfma2u(uq0[2], w0.z, a0);  a1 = hfma2u(uq0[3], w0.w, a1);
        b0 = hfma2u(uq1[2], w0.z, b0);  b1 = hfma2u(uq1[3], w0.w, b1);

#define VQ_STEP(W, B) \
        a0 = hfma2u(uq0[B + 0], W.x, a0);  a1 = hfma2u(uq0[B + 1], W.y, a1); \
        b0 = hfma2u(uq1[B + 0], W.x, b0);  b1 = hfma2u(uq1[B + 1], W.y, b1); \
        a0 = hfma2u(uq0[B + 2], W.z, a0);  a1 = hfma2u(uq0[B + 3], W.w, a1); \
        b0 = hfma2u(uq1[B + 2], W.z, b0);  b1 = hfma2u(uq1[B + 3], W.w, b1);

        VQ_STEP(w1, 4)  VQ_STEP(w2, 8)  VQ_STEP(w3, 12) VQ_STEP(w4, 16)
        VQ_STEP(w5, 20) VQ_STEP(w6, 24) VQ_STEP(w7, 28)
#undef VQ_STEP

        const uint32_t sa = hadd2u(a0, a1);
        const uint32_t sb = hadd2u(b0, b1);
        const __half s0 = __hadd(__ushort_as_half((unsigned short)(sa & 0xFFFFu)),
                                 __ushort_as_half((unsigned short)(sa >> 16)));
        const __half s1 = __hadd(__ushort_as_half((unsigned short)(sb & 0xFFFFu)),
                                 __ushort_as_half((unsigned short)(sb >> 16)));

        if (__hle(s0, thr0)) {                 // rare branch
            cand0[cnt0 & (CAP - 1)] = j; cnt0++;
            thr0 = __hmin(thr0, __hadd(s0, hm0));
        }
        if (__hle(s1, thr1)) {
            cand1[cnt1 & (CAP - 1)] = j; cnt1++;
            thr1 = __hmin(thr1, __hadd(s1, hm1));
        }
    }
    g_ccount[row0] = cnt0;
    g_ccount[row1] = cnt1;
}

// ---------------------------------------------------------------------------
// Kernel 3: exact fp32 recheck + fused epilogue. One warp per row.
// ---------------------------------------------------------------------------
__global__ void __launch_bounds__(256)
vq_recheck(const float* __restrict__ z, const float* __restrict__ cb,
           float* __restrict__ out_idxf, float* __restrict__ out_zq) {
    const int lane = threadIdx.x & 31;
    const int w = threadIdx.x >> 5;
    const int row = blockIdx.x * 8 + w;

    float4 zr[16];
    const float4* zp = reinterpret_cast<const float4*>(z + (size_t)row * E_DIM);
#pragma unroll
    for (int i = 0; i < 16; i++) zr[i] = zp[i];

    float zz = 0.0f;
#pragma unroll
    for (int i = 0; i < 16; i++) {
        float4 v = zr[i];
        zz = fmaf(v.x, v.x, zz);
        zz = fmaf(v.y, v.y, zz);
        zz = fmaf(v.z, v.z, zz);
        zz = fmaf(v.w, v.w, zz);
    }

    int n = g_ccount[row];
    bool full = (n > CAP);
    int n_eff = full ? N_CODE : n;

    unsigned long long best = 0xffffffffffffffffull;
    for (int i = lane; i < n_eff; i += 32) {
        int j = full ? i : g_cand[(size_t)row * CAP + i];
        const float4* ep = reinterpret_cast<const float4*>(cb + (size_t)j * E_DIM);
        float dot = dot64(zr, ep);
        float d = fmaf(-2.0f, dot, zz + __ldg(&g_cc[j]));
        unsigned long long pk =
            ((unsigned long long)__float_as_uint(d) << 32) | (unsigned)j;
        best = min(best, pk);
    }
#pragma unroll
    for (int off = 16; off > 0; off >>= 1)
        best = min(best, __shfl_xor_sync(0xffffffff, best, off));
    const int bi = (int)(best & 0xffffffffu);

    if (lane == 0) {
        g_idx[row] = bi;
        out_idxf[row] = (float)bi;
        atomicAdd(&g_counts[bi], 1);
    }

    // fused epilogue (out_zq = out+1 is only 4B aligned -> scalar stores)
    const float2 zf = *reinterpret_cast<const float2*>(z + (size_t)row * E_DIM + 2 * lane);
    const float qx = cb[(size_t)bi * E_DIM + 2 * lane];
    const float qy = cb[(size_t)bi * E_DIM + 2 * lane + 1];
    float dx = qx - zf.x;
    float dy = qy - zf.y;
    float* op = out_zq + (size_t)row * E_DIM + 2 * lane;
    op[0] = zf.x + (qx - zf.x);     // mirror reference STE arithmetic
    op[1] = zf.y + (qy - zf.y);

    float sse = fmaf(dx, dx, dy * dy);
#pragma unroll
    for (int off = 16; off > 0; off >>= 1)
        sse += __shfl_xor_sync(0xffffffff, sse, off);

    __shared__ float wsum[8];
    if (lane == 0) wsum[w] = sse;
    __syncthreads();
    if (threadIdx.x == 0) {
        float s = 0.0f;
#pragma unroll
        for (int k = 0; k < 8; k++) s += wsum[k];
        g_sse_part[blockIdx.x] = s;
    }
}

// ---------------------------------------------------------------------------
// Kernel 4: finalize loss + perplexity
// ---------------------------------------------------------------------------
__global__ void vq_finalize(float* __restrict__ out) {
    __shared__ float red[1024];
    int t = threadIdx.x;

    float s = 0.0f;
#pragma unroll
    for (int k = 0; k < 8; k++) s += g_sse_part[t + k * 1024];
    red[t] = s;
    __syncthreads();
#pragma unroll
    for (int st = 512; st > 0; st >>= 1) {
        if (t < st) red[t] += red[t + st];
        __syncthreads();
    }
    float sse = red[0];
    __syncthreads();

    float c = (float)g_counts[t];
    float em = c * (1.0f / (float)N_VEC);
    red[t] = em * logf(em + 1e-10f);
    __syncthreads();
#pragma unroll
    for (int st = 512; st > 0; st >>= 1) {
        if (t < st) red[t] += red[t + st];
        __syncthreads();
    }
    if (t == 0) {
        float mean = sse * (1.0f / (float)ELEMS);
        out[0] = 1.25f * mean;             // (1 + BETA) * mean((z_q - z)^2)
        out[1 + ELEMS] = expf(-red[0]);    // perplexity
    }
}

// ---------------------------------------------------------------------------
// Launch: out layout = [loss(1) | z_q_st(N*64) | perplexity(1) | idx(N)]
// ---------------------------------------------------------------------------
extern "C" void kernel_launch(void* const* d_in, const int* in_sizes, int n_in,
                              void* d_out, int out_size) {
    const float* z  = (const float*)d_in[0];
    const float* cb = (const float*)d_in[1];
    float* out = (float*)d_out;

    float* out_zq   = out + 1;
    float* out_idxf = out + 2 + ELEMS;

    static bool attr_set = false;
    if (!attr_set) {
        cudaFuncSetAttribute(vq_screen, cudaFuncAttributeMaxDynamicSharedMemorySize,
                             SMEM_SCREEN);
        attr_set = true;
    }

    vq_prep<<<4, 256>>>(cb);
    vq_screen<<<N_VEC / 512, 256, SMEM_SCREEN>>>(z);
    vq_recheck<<<N_VEC / 8, 256>>>(z, cb, out_idxf, out_zq);
    vq_finalize<<<1, 1024>>>(out);
}

// round 13
// speedup vs baseline: 1.1082x; 1.1082x over previous
#include <cuda_runtime.h>
#include <cuda_fp16.h>
#include <cuda_bf16.h>
#include <math_constants.h>
#include <cstdint>

// Problem constants (z: 32*2048*64 fp32, codebook: 1024*64 fp32)
#define N_VEC   65536
#define E_DIM   64
#define N_CODE  1024
#define ELEMS   (N_VEC * E_DIM)
#define CAP     64

// ---------------------------------------------------------------------------
// Global scratch (module globals; no runtime allocation)
// ---------------------------------------------------------------------------
__device__ float    g_cc[N_CODE];
__device__ uint16_t g_cch[N_CODE];            // fp16 bits of cc/2
__device__ __half2  g_cb_h[N_CODE * 32];      // fp16 codebook, [code][32 half2]
__device__ int      g_idx[N_VEC];
__device__ int      g_counts[N_CODE];
__device__ float    g_sse_part[8192];
__device__ int      g_ccount[N_VEC];
__device__ int      g_cand[N_VEC * CAP];

// ---------------------------------------------------------------------------
// helpers — packed fp16 math on plain uint32 registers
// ---------------------------------------------------------------------------
__device__ __forceinline__ uint32_t hfma2u(uint32_t a, uint32_t b, uint32_t c) {
    uint32_t d;
    asm("fma.rn.f16x2 %0, %1, %2, %3;" : "=r"(d) : "r"(a), "r"(b), "r"(c));
    return d;
}
__device__ __forceinline__ uint32_t hadd2u(uint32_t a, uint32_t b) {
    uint32_t d;
    asm("add.rn.f16x2 %0, %1, %2;" : "=r"(d) : "r"(a), "r"(b));
    return d;
}
__device__ __forceinline__ uint32_t packn_h2(float x, float y) {   // fp16(-x),fp16(-y)
    __half2_raw r = __floats2half2_rn(-x, -y);
    return (uint32_t)r.x | ((uint32_t)r.y << 16);
}

// exact fp32 dot — identical chain to the rel_err-0.0 passing rounds
__device__ __forceinline__ float dot64(const float4* __restrict__ a,
                                       const float4* __restrict__ b) {
    float s = 0.0f;
#pragma unroll
    for (int i = 0; i < 16; i++) {
        float4 x = a[i], y = b[i];
        s = fmaf(x.x, y.x, s);
        s = fmaf(x.y, y.y, s);
        s = fmaf(x.z, y.z, s);
        s = fmaf(x.w, y.w, s);
    }
    return s;
}

// ---------------------------------------------------------------------------
// Kernel 1: cc norms, fp16 codebook + cc/2, zero histogram. 4 blocks x 256.
// ---------------------------------------------------------------------------
__global__ void vq_prep(const float* __restrict__ cb) {
    const int j = blockIdx.x * 256 + threadIdx.x;     // 0..1023
    const float4* p = reinterpret_cast<const float4*>(cb + (size_t)j * E_DIM);
    float s = 0.0f;
#pragma unroll
    for (int i = 0; i < 16; i++) {
        float4 v = p[i];
        s = fmaf(v.x, v.x, s);
        s = fmaf(v.y, v.y, s);
        s = fmaf(v.z, v.z, s);
        s = fmaf(v.w, v.w, s);
        g_cb_h[j * 32 + 2 * i]     = __floats2half2_rn(v.x, v.y);
        g_cb_h[j * 32 + 2 * i + 1] = __floats2half2_rn(v.z, v.w);
    }
    g_cc[j] = s;
    g_cch[j] = __half_as_ushort(__float2half(0.5f * s));
    g_counts[j] = 0;
}

// ---------------------------------------------------------------------------
// Kernel 2: clean HFMA2 screening. 128 CTAs x 512 threads, 1 row/thread.
//   16 warps/SM (4 per SMSP) for latency hiding; whole fp16 codebook in smem;
//   double-buffered code loads (j+1 prefetched while j computes).
//   Score s_j = cc_j/2 + sum((-z)*e)  (== (d_j - zz)/2, same ordering).
// ---------------------------------------------------------------------------
#define SMEM_SCREEN (N_CODE * 64 * 2 + N_CODE * 2)    // 133120 B

__global__ void __launch_bounds__(512, 1)
vq_screen(const float* __restrict__ z) {
    extern __shared__ uint4 sE[];                      // 8 uint4 per code
    uint16_t* scch = reinterpret_cast<uint16_t*>(sE + N_CODE * 8);

    const int tid = threadIdx.x;
    const int row = blockIdx.x * 512 + tid;

    // stage codebook (8192 uint4, 16 per thread) + cc/2 (as u32 pairs)
    {
        const uint4* src = reinterpret_cast<const uint4*>(g_cb_h);
#pragma unroll
        for (int k = 0; k < 16; k++)
            sE[k * 512 + tid] = src[k * 512 + tid];
        const uint32_t* cs = reinterpret_cast<const uint32_t*>(g_cch);
        uint32_t* cd = reinterpret_cast<uint32_t*>(scch);
        if (tid < 512) cd[tid & 511] = cs[tid & 511];
    }

    // load z row -> negated fp16 pair regs (const-indexed, fully unrolled)
    uint32_t uq[32];
    float sz = 0.0f;
    {
        const float4* zp = reinterpret_cast<const float4*>(z + (size_t)row * E_DIM);
#pragma unroll
        for (int i = 0; i < 16; i++) {
            float4 v = zp[i];
            sz += fabsf(v.x) + fabsf(v.y) + fabsf(v.z) + fabsf(v.w);
            uq[2 * i]     = packn_h2(v.x, v.y);
            uq[2 * i + 1] = packn_h2(v.z, v.w);
        }
    }
    const __half hm = __float2half(sz * 2e-5f + 2e-4f);   // validated margin form

    __syncthreads();

    __half thr = __ushort_as_half((unsigned short)0x7C00);  // +inf
    int cnt = 0;
    int* cand = g_cand + (size_t)row * CAP;

    // double-buffered pipeline over codes
    uint4 w0 = sE[0], w1 = sE[1], w2 = sE[2], w3 = sE[3];
    uint4 w4 = sE[4], w5 = sE[5], w6 = sE[6], w7 = sE[7];

    for (int j = 0; j < N_CODE; j++) {
        // prefetch code j+1 into the alternate register set
        const uint4* np = sE + ((j + 1) & (N_CODE - 1)) * 8;
        const uint4 n0 = np[0], n1 = np[1], n2 = np[2], n3 = np[3];
        const uint4 n4 = np[4], n5 = np[5], n6 = np[6], n7 = np[7];

        const uint32_t seed = (uint32_t)scch[j];      // cc/2 in LOW half

        uint32_t a0 = hfma2u(uq[0], w0.x, seed);
        uint32_t a1 = hfma2u(uq[1], w0.y, 0u);
        uint32_t a2 = hfma2u(uq[2], w0.z, 0u);
        uint32_t a3 = hfma2u(uq[3], w0.w, 0u);
#define VQ_STEP(W, B) \
        a0 = hfma2u(uq[B + 0], W.x, a0);  a1 = hfma2u(uq[B + 1], W.y, a1); \
        a2 = hfma2u(uq[B + 2], W.z, a2);  a3 = hfma2u(uq[B + 3], W.w, a3);
        VQ_STEP(w1, 4)  VQ_STEP(w2, 8)  VQ_STEP(w3, 12) VQ_STEP(w4, 16)
        VQ_STEP(w5, 20) VQ_STEP(w6, 24) VQ_STEP(w7, 28)
#undef VQ_STEP

        const uint32_t sa = hadd2u(hadd2u(a0, a1), hadd2u(a2, a3));
        const __half s = __hadd(__ushort_as_half((unsigned short)(sa & 0xFFFFu)),
                                __ushort_as_half((unsigned short)(sa >> 16)));

        if (__hle(s, thr)) {                   // rare branch (~10/1024)
            cand[cnt & (CAP - 1)] = j; cnt++;
            thr = __hmin(thr, __hadd(s, hm));
        }

        // rotate buffers
        w0 = n0; w1 = n1; w2 = n2; w3 = n3;
        w4 = n4; w5 = n5; w6 = n6; w7 = n7;
    }
    g_ccount[row] = cnt;
}

// ---------------------------------------------------------------------------
// Kernel 3: exact fp32 recheck + fused epilogue. One warp per row.
// ---------------------------------------------------------------------------
__global__ void __launch_bounds__(256)
vq_recheck(const float* __restrict__ z, const float* __restrict__ cb,
           float* __restrict__ out_idxf, float* __restrict__ out_zq) {
    const int lane = threadIdx.x & 31;
    const int w = threadIdx.x >> 5;
    const int row = blockIdx.x * 8 + w;

    float4 zr[16];
    const float4* zp = reinterpret_cast<const float4*>(z + (size_t)row * E_DIM);
#pragma unroll
    for (int i = 0; i < 16; i++) zr[i] = zp[i];

    float zz = 0.0f;
#pragma unroll
    for (int i = 0; i < 16; i++) {
        float4 v = zr[i];
        zz = fmaf(v.x, v.x, zz);
        zz = fmaf(v.y, v.y, zz);
        zz = fmaf(v.z, v.z, zz);
        zz = fmaf(v.w, v.w, zz);
    }

    int n = g_ccount[row];
    bool full = (n > CAP);
    int n_eff = full ? N_CODE : n;

    unsigned long long best = 0xffffffffffffffffull;
    for (int i = lane; i < n_eff; i += 32) {
        int j = full ? i : g_cand[(size_t)row * CAP + i];
        const float4* ep = reinterpret_cast<const float4*>(cb + (size_t)j * E_DIM);
        float dot = dot64(zr, ep);
        float d = fmaf(-2.0f, dot, zz + __ldg(&g_cc[j]));
        unsigned long long pk =
            ((unsigned long long)__float_as_uint(d) << 32) | (unsigned)j;
        best = min(best, pk);
    }
#pragma unroll
    for (int off = 16; off > 0; off >>= 1)
        best = min(best, __shfl_xor_sync(0xffffffff, best, off));
    const int bi = (int)(best & 0xffffffffu);

    if (lane == 0) {
        g_idx[row] = bi;
        out_idxf[row] = (float)bi;
        atomicAdd(&g_counts[bi], 1);
    }

    // fused epilogue (out_zq = out+1 is only 4B aligned -> scalar stores)
    const float2 zf = *reinterpret_cast<const float2*>(z + (size_t)row * E_DIM + 2 * lane);
    const float qx = cb[(size_t)bi * E_DIM + 2 * lane];
    const float qy = cb[(size_t)bi * E_DIM + 2 * lane + 1];
    float dx = qx - zf.x;
    float dy = qy - zf.y;
    float* op = out_zq + (size_t)row * E_DIM + 2 * lane;
    op[0] = zf.x + (qx - zf.x);     // mirror reference STE arithmetic
    op[1] = zf.y + (qy - zf.y);

    float sse = fmaf(dx, dx, dy * dy);
#pragma unroll
    for (int off = 16; off > 0; off >>= 1)
        sse += __shfl_xor_sync(0xffffffff, sse, off);

    __shared__ float wsum[8];
    if (lane == 0) wsum[w] = sse;
    __syncthreads();
    if (threadIdx.x == 0) {
        float s = 0.0f;
#pragma unroll
        for (int k = 0; k < 8; k++) s += wsum[k];
        g_sse_part[blockIdx.x] = s;
    }
}

// ---------------------------------------------------------------------------
// Kernel 4: finalize loss + perplexity
// ---------------------------------------------------------------------------
__global__ void vq_finalize(float* __restrict__ out) {
    __shared__ float red[1024];
    int t = threadIdx.x;

    float s = 0.0f;
#pragma unroll
    for (int k = 0; k < 8; k++) s += g_sse_part[t + k * 1024];
    red[t] = s;
    __syncthreads();
#pragma unroll
    for (int st = 512; st > 0; st >>= 1) {
        if (t < st) red[t] += red[t + st];
        __syncthreads();
    }
    float sse = red[0];
    __syncthreads();

    float c = (float)g_counts[t];
    float em = c * (1.0f / (float)N_VEC);
    red[t] = em * logf(em + 1e-10f);
    __syncthreads();
#pragma unroll
    for (int st = 512; st > 0; st >>= 1) {
        if (t < st) red[t] += red[t + st];
        __syncthreads();
    }
    if (t == 0) {
        float mean = sse * (1.0f / (float)ELEMS);
        out[0] = 1.25f * mean;             // (1 + BETA) * mean((z_q - z)^2)
        out[1 + ELEMS] = expf(-red[0]);    // perplexity
    }
}

// ---------------------------------------------------------------------------
// Launch: out layout = [loss(1) | z_q_st(N*64) | perplexity(1) | idx(N)]
// ---------------------------------------------------------------------------
extern "C" void kernel_launch(void* const* d_in, const int* in_sizes, int n_in,
                              void* d_out, int out_size) {
    const float* z  = (const float*)d_in[0];
    const float* cb = (const float*)d_in[1];
    float* out = (float*)d_out;

    float* out_zq   = out + 1;
    float* out_idxf = out + 2 + ELEMS;

    static bool attr_set = false;
    if (!attr_set) {
        cudaFuncSetAttribute(vq_screen, cudaFuncAttributeMaxDynamicSharedMemorySize,
                             SMEM_SCREEN);
        attr_set = true;
    }

    vq_prep<<<4, 256>>>(cb);
    vq_screen<<<N_VEC / 512, 512, SMEM_SCREEN>>>(z);
    vq_recheck<<<N_VEC / 8, 256>>>(z, cb, out_idxf, out_zq);
    vq_finalize<<<1, 1024>>>(out);
}